// round 1
// baseline (speedup 1.0000x reference)
#include <cuda_runtime.h>
#include <math.h>

// Problem constants
#define Bq     8
#define Sq     16384          // 128*128
#define Eq     384
#define Hh     8
#define Dd     48
#define FFq    1536
#define MROWS  (Bq*Sq)        // 131072
#define EPSq   1e-5f

// ---------------- scratch (device globals; no allocation allowed) -----------
__device__ float2 g_stats[MROWS];
__device__ float  g_qkv[(size_t)MROWS * 1152];   // 604 MB
__device__ float  g_o  [(size_t)MROWS * Eq];     // 201 MB
__device__ float  g_x1 [(size_t)MROWS * Eq];     // 201 MB
__device__ float  g_h  [(size_t)MROWS * FFq];    // 805 MB

// ---------------- per-row mean/rstd (E = 384) -------------------------------
__global__ void __launch_bounds__(256) row_stats_k(const float* __restrict__ X,
                                                   float2* __restrict__ st) {
    int row  = blockIdx.x * 8 + (threadIdx.x >> 5);
    int lane = threadIdx.x & 31;
    const float4* x = (const float4*)(X + (size_t)row * Eq);
    float s = 0.f, ss = 0.f;
#pragma unroll
    for (int j = 0; j < 3; ++j) {                 // 384/4/32 = 3
        float4 v = x[lane + 32 * j];
        s  += v.x + v.y + v.z + v.w;
        ss += v.x * v.x + v.y * v.y + v.z * v.z + v.w * v.w;
    }
#pragma unroll
    for (int o = 16; o; o >>= 1) {
        s  += __shfl_xor_sync(0xffffffffu, s,  o);
        ss += __shfl_xor_sync(0xffffffffu, ss, o);
    }
    if (lane == 0) {
        float m   = s * (1.f / Eq);
        float var = ss * (1.f / Eq) - m * m;
        st[row] = make_float2(m, rsqrtf(var + EPSq));
    }
}

// ---------------- SGEMM: C[M,N] = op( A[M,K] (opt-LN) @ W[N,K]^T + bias ) ----
// EPI: 0 = +bias ; 1 = +bias then erf-GELU ; 2 = +bias + residual
template<bool LN, int EPI>
__global__ void __launch_bounds__(256, 2) gemm_k(
    const float*  __restrict__ A,   const float* __restrict__ W,
    const float*  __restrict__ bias,const float* __restrict__ resid,
    const float2* __restrict__ stats,
    const float*  __restrict__ gamma, const float* __restrict__ beta,
    float* __restrict__ C, int K, int N)
{
    __shared__ float As[16][128];
    __shared__ float Bs[16][128];
    const int tid = threadIdx.x;
    const int m0  = blockIdx.y * 128;
    const int n0  = blockIdx.x * 128;
    const int tx  = tid & 15, ty = tid >> 4;

    float acc[8][8];
#pragma unroll
    for (int i = 0; i < 8; ++i)
#pragma unroll
        for (int j = 0; j < 8; ++j) acc[i][j] = 0.f;

    const int r0  = tid >> 2;          // 0..63
    const int c40 = tid & 3;           // float4 column within 16-wide K chunk
    float2 st0, st1;
    if (LN) { st0 = stats[m0 + r0]; st1 = stats[m0 + r0 + 64]; }
    const float* Arow0 = A + (size_t)(m0 + r0) * K + c40 * 4;
    const float* Arow1 = Arow0 + (size_t)64 * K;
    const float* Wrow0 = W + (size_t)(n0 + r0) * K + c40 * 4;
    const float* Wrow1 = Wrow0 + (size_t)64 * K;

    for (int kt = 0; kt < K; kt += 16) {
        float4 a0 = *(const float4*)(Arow0 + kt);
        float4 a1 = *(const float4*)(Arow1 + kt);
        float4 w0 = *(const float4*)(Wrow0 + kt);
        float4 w1 = *(const float4*)(Wrow1 + kt);
        if (LN) {
            int kg = kt + c40 * 4;
            float4 g4 = *(const float4*)(gamma + kg);
            float4 b4 = *(const float4*)(beta  + kg);
            a0.x = (a0.x - st0.x) * st0.y * g4.x + b4.x;
            a0.y = (a0.y - st0.x) * st0.y * g4.y + b4.y;
            a0.z = (a0.z - st0.x) * st0.y * g4.z + b4.z;
            a0.w = (a0.w - st0.x) * st0.y * g4.w + b4.w;
            a1.x = (a1.x - st1.x) * st1.y * g4.x + b4.x;
            a1.y = (a1.y - st1.x) * st1.y * g4.y + b4.y;
            a1.z = (a1.z - st1.x) * st1.y * g4.z + b4.z;
            a1.w = (a1.w - st1.x) * st1.y * g4.w + b4.w;
        }
        __syncthreads();   // previous compute done before smem overwrite
        int c = c40 * 4;
        As[c + 0][r0] = a0.x; As[c + 1][r0] = a0.y; As[c + 2][r0] = a0.z; As[c + 3][r0] = a0.w;
        As[c + 0][r0 + 64] = a1.x; As[c + 1][r0 + 64] = a1.y; As[c + 2][r0 + 64] = a1.z; As[c + 3][r0 + 64] = a1.w;
        Bs[c + 0][r0] = w0.x; Bs[c + 1][r0] = w0.y; Bs[c + 2][r0] = w0.z; Bs[c + 3][r0] = w0.w;
        Bs[c + 0][r0 + 64] = w1.x; Bs[c + 1][r0 + 64] = w1.y; Bs[c + 2][r0 + 64] = w1.z; Bs[c + 3][r0 + 64] = w1.w;
        __syncthreads();
#pragma unroll
        for (int kk = 0; kk < 16; ++kk) {
            float4 aA = *(const float4*)&As[kk][ty * 8];
            float4 aB = *(const float4*)&As[kk][ty * 8 + 4];
            float4 bA = *(const float4*)&Bs[kk][tx * 8];
            float4 bB = *(const float4*)&Bs[kk][tx * 8 + 4];
            float a[8] = {aA.x, aA.y, aA.z, aA.w, aB.x, aB.y, aB.z, aB.w};
            float b[8] = {bA.x, bA.y, bA.z, bA.w, bB.x, bB.y, bB.z, bB.w};
#pragma unroll
            for (int i = 0; i < 8; ++i)
#pragma unroll
                for (int j = 0; j < 8; ++j) acc[i][j] += a[i] * b[j];
        }
    }

    float4 bb0 = *(const float4*)(bias + n0 + tx * 8);
    float4 bb1 = *(const float4*)(bias + n0 + tx * 8 + 4);
#pragma unroll
    for (int i = 0; i < 8; ++i) {
        int r = m0 + ty * 8 + i;
        size_t base = (size_t)r * N + n0 + tx * 8;
        float4 o0, o1;
        o0.x = acc[i][0] + bb0.x; o0.y = acc[i][1] + bb0.y;
        o0.z = acc[i][2] + bb0.z; o0.w = acc[i][3] + bb0.w;
        o1.x = acc[i][4] + bb1.x; o1.y = acc[i][5] + bb1.y;
        o1.z = acc[i][6] + bb1.z; o1.w = acc[i][7] + bb1.w;
        if (EPI == 1) {
            o0.x = 0.5f * o0.x * (1.f + erff(o0.x * 0.70710678118654752f));
            o0.y = 0.5f * o0.y * (1.f + erff(o0.y * 0.70710678118654752f));
            o0.z = 0.5f * o0.z * (1.f + erff(o0.z * 0.70710678118654752f));
            o0.w = 0.5f * o0.w * (1.f + erff(o0.w * 0.70710678118654752f));
            o1.x = 0.5f * o1.x * (1.f + erff(o1.x * 0.70710678118654752f));
            o1.y = 0.5f * o1.y * (1.f + erff(o1.y * 0.70710678118654752f));
            o1.z = 0.5f * o1.z * (1.f + erff(o1.z * 0.70710678118654752f));
            o1.w = 0.5f * o1.w * (1.f + erff(o1.w * 0.70710678118654752f));
        }
        if (EPI == 2) {
            float4 rA = *(const float4*)(resid + base);
            float4 rB = *(const float4*)(resid + base + 4);
            o0.x += rA.x; o0.y += rA.y; o0.z += rA.z; o0.w += rA.w;
            o1.x += rB.x; o1.y += rB.y; o1.z += rB.z; o1.w += rB.w;
        }
        *(float4*)(C + base)     = o0;
        *(float4*)(C + base + 4) = o1;
    }
}

// ---------------- attention over batch axis (len 8) per (s, head) -----------
// One CTA per s; warp h handles head h. Row stride 1156 floats: batch rows
// land 4 banks apart -> conflict-free float4 dot products.
#define QSTRIDE 1156
__global__ void __launch_bounds__(256) attn_k(const float* __restrict__ qkv,
                                              float* __restrict__ o) {
    __shared__ float sq[8 * QSTRIDE];       // 36.1 KB
    __shared__ float sc[8][64];
    const int s   = blockIdx.x;
    const int tid = threadIdx.x;

#pragma unroll
    for (int j = 0; j < 9; ++j) {           // 8*288 = 2304 float4 loads
        int i  = tid + j * 256;
        int b  = i / 288, jj = i % 288;
        float4 v = *(const float4*)(qkv + ((size_t)(b * Sq + s)) * 1152 + jj * 4);
        *(float4*)(sq + b * QSTRIDE + jj * 4) = v;
    }
    __syncthreads();

    const int h = tid >> 5, lane = tid & 31;
    const float scale = 0.14433756729740644f;   // 1/sqrt(48)

    {   // scores: 64 per head, 2 per lane
        int idx0 = lane, idx1 = lane + 32;
        int b0 = idx0 >> 3, c0 = idx0 & 7;
        int b1 = idx1 >> 3, c1 = idx1 & 7;
        const float4* q0 = (const float4*)(sq + b0 * QSTRIDE + h * 48);
        const float4* k0 = (const float4*)(sq + c0 * QSTRIDE + 384 + h * 48);
        const float4* q1 = (const float4*)(sq + b1 * QSTRIDE + h * 48);
        const float4* k1 = (const float4*)(sq + c1 * QSTRIDE + 384 + h * 48);
        float s0 = 0.f, s1 = 0.f;
#pragma unroll
        for (int d4 = 0; d4 < 12; ++d4) {
            float4 qa = q0[d4], ka = k0[d4];
            s0 += qa.x * ka.x + qa.y * ka.y + qa.z * ka.z + qa.w * ka.w;
            float4 qb = q1[d4], kb = k1[d4];
            s1 += qb.x * kb.x + qb.y * kb.y + qb.z * kb.z + qb.w * kb.w;
        }
        sc[h][idx0] = s0 * scale;
        sc[h][idx1] = s1 * scale;
    }
    __syncwarp();

    if (lane < 8) {                          // softmax over c for row b=lane
        float e[8]; float mx = -1e30f;
#pragma unroll
        for (int c = 0; c < 8; ++c) { e[c] = sc[h][lane * 8 + c]; mx = fmaxf(mx, e[c]); }
        float sum = 0.f;
#pragma unroll
        for (int c = 0; c < 8; ++c) { e[c] = expf(e[c] - mx); sum += e[c]; }
        float inv = 1.f / sum;
#pragma unroll
        for (int c = 0; c < 8; ++c) sc[h][lane * 8 + c] = e[c] * inv;
    }
    __syncwarp();

#pragma unroll
    for (int j = 0; j < 3; ++j) {            // 96 float4 outputs per head
        int e4 = lane + j * 32;
        int b = e4 / 12, d4 = e4 % 12;
        float4 acc = make_float4(0.f, 0.f, 0.f, 0.f);
#pragma unroll
        for (int c = 0; c < 8; ++c) {
            float p = sc[h][b * 8 + c];
            float4 v = *(const float4*)(sq + c * QSTRIDE + 768 + h * 48 + d4 * 4);
            acc.x += p * v.x; acc.y += p * v.y; acc.z += p * v.z; acc.w += p * v.w;
        }
        *(float4*)(o + ((size_t)(b * Sq + s)) * 384 + h * 48 + d4 * 4) = acc;
    }
}

// ---------------- launch -----------------------------------------------------
extern "C" void kernel_launch(void* const* d_in, const int* in_sizes, int n_in,
                              void* d_out, int out_size) {
    const float* x     = (const float*)d_in[0];
    const float* in_w  = (const float*)d_in[1];
    const float* in_b  = (const float*)d_in[2];
    const float* out_w = (const float*)d_in[3];
    const float* out_b = (const float*)d_in[4];
    const float* ln1g  = (const float*)d_in[5];
    const float* ln1b  = (const float*)d_in[6];
    const float* ln2g  = (const float*)d_in[7];
    const float* ln2b  = (const float*)d_in[8];
    const float* w1    = (const float*)d_in[9];
    const float* b1    = (const float*)d_in[10];
    const float* w2    = (const float*)d_in[11];
    const float* b2    = (const float*)d_in[12];
    float* out = (float*)d_out;

    float2* stats; float *qkv, *obuf, *x1, *hbuf;
    cudaGetSymbolAddress((void**)&stats, g_stats);
    cudaGetSymbolAddress((void**)&qkv,   g_qkv);
    cudaGetSymbolAddress((void**)&obuf,  g_o);
    cudaGetSymbolAddress((void**)&x1,    g_x1);
    cudaGetSymbolAddress((void**)&hbuf,  g_h);

    // 1) LN1 stats
    row_stats_k<<<MROWS / 8, 256>>>(x, stats);
    // 2) QKV = LN1(x) @ in_proj_w^T + in_proj_b
    dim3 gqkv(1152 / 128, MROWS / 128);
    gemm_k<true, 0><<<gqkv, 256>>>(x, in_w, in_b, nullptr, stats, ln1g, ln1b,
                                   qkv, Eq, 1152);
    // 3) batch-axis attention per (s, head)
    attn_k<<<Sq, 256>>>(qkv, obuf);
    // 4) x1 = x + o @ out_w^T + out_b
    dim3 gout(Eq / 128, MROWS / 128);
    gemm_k<false, 2><<<gout, 256>>>(obuf, out_w, out_b, x, nullptr, nullptr, nullptr,
                                    x1, Eq, Eq);
    // 5) LN2 stats
    row_stats_k<<<MROWS / 8, 256>>>(x1, stats);
    // 6) h = gelu( LN2(x1) @ w1^T + b1 )
    dim3 gff1(FFq / 128, MROWS / 128);
    gemm_k<true, 1><<<gff1, 256>>>(x1, w1, b1, nullptr, stats, ln2g, ln2b,
                                   hbuf, Eq, FFq);
    // 7) out = x1 + h @ w2^T + b2
    gemm_k<false, 2><<<gout, 256>>>(hbuf, w2, b2, x1, nullptr, nullptr, nullptr,
                                    out, FFq, Eq);
}

// round 5
// speedup vs baseline: 2.3065x; 2.3065x over previous
#include <cuda_runtime.h>
#include <cstdint>
#include <math.h>

// Problem constants
#define Bq     8
#define Sq     16384          // 128*128
#define Eq     384
#define FFq    1536
#define MROWS  (Bq*Sq)        // 131072
#define EPSq   1e-5f
#define NQKV   1152

// ---------------- scratch (device globals; no allocation allowed) -----------
__device__ float2 g_stats[MROWS];
__device__ float  g_qkv[(size_t)MROWS * NQKV];   // 604 MB
__device__ float  g_o  [(size_t)MROWS * Eq];     // 201 MB
__device__ float  g_x1 [(size_t)MROWS * Eq];     // 201 MB
__device__ float  g_h  [(size_t)MROWS * FFq];    // 805 MB
__device__ float  g_wqkv[NQKV * Eq];             // g-scaled, tf32-rounded in_proj_w
__device__ float  g_w1p [FFq * Eq];              // g-scaled, tf32-rounded w1
__device__ float  g_owp [Eq * Eq];               // tf32-rounded out_w
__device__ float  g_w2p [Eq * FFq];              // tf32-rounded w2
__device__ float  g_c1q[NQKV], g_c2q[NQKV];
__device__ float  g_c1f[FFq],  g_c2f[FFq];

// ---------------- PTX helpers ------------------------------------------------
__device__ __forceinline__ uint32_t smem_u32(const void* p) {
    uint32_t a;
    asm("{ .reg .u64 t; cvta.to.shared.u64 t, %1; cvt.u32.u64 %0, t; }"
        : "=r"(a) : "l"(p));
    return a;
}
__device__ __forceinline__ void cp16(uint32_t s, const void* g) {
    asm volatile("cp.async.cg.shared.global [%0], [%1], 16;\n" :: "r"(s), "l"(g));
}
__device__ __forceinline__ void cp_commit() {
    asm volatile("cp.async.commit_group;\n" ::: "memory");
}
template<int N> __device__ __forceinline__ void cp_wait() {
    asm volatile("cp.async.wait_group %0;\n" :: "n"(N) : "memory");
}
__device__ __forceinline__ uint32_t cvt_tf32(float f) {
    uint32_t r;
    asm("cvt.rna.tf32.f32 %0, %1;" : "=r"(r) : "f"(f));
    return r;
}
__device__ __forceinline__ float tf32_round(float f) {
    return __uint_as_float(cvt_tf32(f));
}
__device__ __forceinline__ void mma_tf32(float* c, const uint32_t* a, const uint32_t* b) {
    asm volatile(
        "mma.sync.aligned.m16n8k8.row.col.f32.tf32.tf32.f32 "
        "{%0,%1,%2,%3}, {%4,%5,%6,%7}, {%8,%9}, {%0,%1,%2,%3};\n"
        : "+f"(c[0]), "+f"(c[1]), "+f"(c[2]), "+f"(c[3])
        : "r"(a[0]), "r"(a[1]), "r"(a[2]), "r"(a[3]), "r"(b[0]), "r"(b[1]));
}

// ---------------- per-row mean/rstd (E = 384) -------------------------------
__global__ void __launch_bounds__(256) row_stats_k(const float* __restrict__ X,
                                                   float2* __restrict__ st) {
    int row  = blockIdx.x * 8 + (threadIdx.x >> 5);
    int lane = threadIdx.x & 31;
    const float4* x = (const float4*)(X + (size_t)row * Eq);
    float s = 0.f, ss = 0.f;
#pragma unroll
    for (int j = 0; j < 3; ++j) {
        float4 v = x[lane + 32 * j];
        s  += v.x + v.y + v.z + v.w;
        ss += v.x * v.x + v.y * v.y + v.z * v.z + v.w * v.w;
    }
#pragma unroll
    for (int o = 16; o; o >>= 1) {
        s  += __shfl_xor_sync(0xffffffffu, s,  o);
        ss += __shfl_xor_sync(0xffffffffu, ss, o);
    }
    if (lane == 0) {
        float m   = s * (1.f / Eq);
        float var = ss * (1.f / Eq) - m * m;
        st[row] = make_float2(m, rsqrtf(var + EPSq));
    }
}

// ---- LN fold prep: Wp = rnd_tf32(W*g), c1 = sum Wp, c2 = sum be*W + bias ----
__global__ void __launch_bounds__(128) prep_k(const float* __restrict__ W,
                                              const float* __restrict__ bias,
                                              const float* __restrict__ g,
                                              const float* __restrict__ be,
                                              float* __restrict__ Wp,
                                              float* __restrict__ c1,
                                              float* __restrict__ c2, int K) {
    int n = blockIdx.x, t = threadIdx.x;
    float s1 = 0.f, s2 = 0.f;
    for (int k = t; k < K; k += 128) {
        float w  = W[(size_t)n * K + k];
        float wp = tf32_round(w * g[k]);
        Wp[(size_t)n * K + k] = wp;
        s1 += wp;
        s2 += w * be[k];
    }
    __shared__ float r1[128], r2[128];
    r1[t] = s1; r2[t] = s2;
    __syncthreads();
    for (int o = 64; o; o >>= 1) {
        if (t < o) { r1[t] += r1[t + o]; r2[t] += r2[t + o]; }
        __syncthreads();
    }
    if (t == 0) { c1[n] = r1[0]; c2[n] = r2[0] + bias[n]; }
}

// ---- plain tf32 rounding of a weight matrix --------------------------------
__global__ void __launch_bounds__(256) round_w_k(const float* __restrict__ W,
                                                 float* __restrict__ Wp, int n) {
    int i = blockIdx.x * 256 + threadIdx.x;
    if (i < n) Wp[i] = tf32_round(W[i]);
}

// ---------------- tf32 mma.sync GEMM: C = A[M,K] @ W[N,K]^T (+epilogue) -----
// EPI 0: LN fold (r*acc - rm*c1 + c2)
// EPI 1: LN fold + erf-GELU
// EPI 2: + bias + residual
#define BKq      32
#define ASTRIDE  36                       // padded row stride (floats)
#define STAGE_F  (2 * 128 * ASTRIDE)      // A block + B block, floats
#define SMEM_GEMM (2 * STAGE_F * 4)       // double buffered, bytes

template<int EPI>
__global__ void __launch_bounds__(256, 2)
tc_gemm(const float* __restrict__ A, const float* __restrict__ W,
        const float* __restrict__ bias, const float* __restrict__ resid,
        const float2* __restrict__ stats, const float* __restrict__ c1,
        const float* __restrict__ c2, float* __restrict__ C, int K, int N)
{
    extern __shared__ float smemf[];
    const uint32_t sbase = smem_u32(smemf);
    const int tid = threadIdx.x;
    const int wid = tid >> 5, lane = tid & 31;
    const int g  = lane >> 2, tg = lane & 3;
    const int n0 = blockIdx.x * 128, m0 = blockIdx.y * 128;
    const int warp_m = wid >> 2, warp_n = wid & 3;       // 2 x 4 warp grid
    const int m_off = warp_m * 64, n_off = warp_n * 32;
    const int T = K / BKq;

    float acc[4][4][4];
#pragma unroll
    for (int mi = 0; mi < 4; ++mi)
#pragma unroll
        for (int ni = 0; ni < 4; ++ni)
#pragma unroll
            for (int j = 0; j < 4; ++j) acc[mi][ni][j] = 0.f;

    // global-load setup: row = tid>>1, half = tid&1 covers 16 floats (4 x cp16)
    const int lr = tid >> 1, lh = tid & 1;
    const char* Ag = (const char*)(A + (size_t)(m0 + lr) * K + lh * 16);
    const char* Bg = (const char*)(W + (size_t)(n0 + lr) * K + lh * 16);
    const uint32_t dA = sbase + (uint32_t)(lr * ASTRIDE + lh * 16) * 4;
    const uint32_t dB = dA + 128 * ASTRIDE * 4;

    auto loadStage = [&](int buf, int kt) {
        const uint32_t so = (uint32_t)buf * STAGE_F * 4;
        const char* ga = Ag + (size_t)kt * BKq * 4;
        const char* gb = Bg + (size_t)kt * BKq * 4;
#pragma unroll
        for (int c = 0; c < 4; ++c) {
            cp16(dA + so + c * 16, ga + c * 16);
            cp16(dB + so + c * 16, gb + c * 16);
        }
    };

    loadStage(0, 0); cp_commit();

    int cur = 0;
    for (int t = 0; t < T; ++t) {
        if (t + 1 < T) loadStage(cur ^ 1, t + 1);
        cp_commit();
        cp_wait<1>();
        __syncthreads();

        const float* sA = smemf + cur * STAGE_F;
        const float* sB = sA + 128 * ASTRIDE;
#pragma unroll
        for (int ks = 0; ks < 4; ++ks) {
            const int k0 = ks * 8;
            uint32_t a[4][4], b[4][2];
#pragma unroll
            for (int mi = 0; mi < 4; ++mi) {
                const float* p = sA + (m_off + mi * 16 + g) * ASTRIDE + k0 + tg;
                a[mi][0] = cvt_tf32(p[0]);
                a[mi][1] = cvt_tf32(p[8 * ASTRIDE]);
                a[mi][2] = cvt_tf32(p[4]);
                a[mi][3] = cvt_tf32(p[8 * ASTRIDE + 4]);
            }
#pragma unroll
            for (int ni = 0; ni < 4; ++ni) {
                const float* p = sB + (n_off + ni * 8 + g) * ASTRIDE + k0 + tg;
                b[ni][0] = __float_as_uint(p[0]);   // weights pre-rounded
                b[ni][1] = __float_as_uint(p[4]);
            }
#pragma unroll
            for (int mi = 0; mi < 4; ++mi)
#pragma unroll
                for (int ni = 0; ni < 4; ++ni)
                    mma_tf32(acc[mi][ni], a[mi], b[ni]);
        }
        __syncthreads();
        cur ^= 1;
    }

    // ---------------- epilogue ----------------
    // acc[mi][ni]: rows m0+m_off+mi*16+{g, g+8}, cols n0+n_off+ni*8+2tg+{0,1}
    float c1v[8], c2v[8];
    if (EPI != 2) {
#pragma unroll
        for (int ni = 0; ni < 4; ++ni) {
            int n = n0 + n_off + ni * 8 + 2 * tg;
            c1v[ni * 2]     = c1[n];     c2v[ni * 2]     = c2[n];
            c1v[ni * 2 + 1] = c1[n + 1]; c2v[ni * 2 + 1] = c2[n + 1];
        }
    } else {
#pragma unroll
        for (int ni = 0; ni < 4; ++ni) {
            int n = n0 + n_off + ni * 8 + 2 * tg;
            c2v[ni * 2]     = bias[n];
            c2v[ni * 2 + 1] = bias[n + 1];
        }
    }

#pragma unroll
    for (int mi = 0; mi < 4; ++mi) {
        const int r0 = m0 + m_off + mi * 16 + g;
        const int r1 = r0 + 8;
        float rr0 = 0.f, rm0 = 0.f, rr1 = 0.f, rm1 = 0.f;
        if (EPI != 2) {
            float2 s0 = stats[r0], s1 = stats[r1];
            rr0 = s0.y; rm0 = s0.x * s0.y;
            rr1 = s1.y; rm1 = s1.x * s1.y;
        }
#pragma unroll
        for (int ni = 0; ni < 4; ++ni) {
            const int n = n0 + n_off + ni * 8 + 2 * tg;
            float v0 = acc[mi][ni][0], v1 = acc[mi][ni][1];
            float v2 = acc[mi][ni][2], v3 = acc[mi][ni][3];
            if (EPI == 0 || EPI == 1) {
                v0 = rr0 * v0 - rm0 * c1v[ni * 2]     + c2v[ni * 2];
                v1 = rr0 * v1 - rm0 * c1v[ni * 2 + 1] + c2v[ni * 2 + 1];
                v2 = rr1 * v2 - rm1 * c1v[ni * 2]     + c2v[ni * 2];
                v3 = rr1 * v3 - rm1 * c1v[ni * 2 + 1] + c2v[ni * 2 + 1];
                if (EPI == 1) {
                    v0 = 0.5f * v0 * (1.f + erff(v0 * 0.70710678118654752f));
                    v1 = 0.5f * v1 * (1.f + erff(v1 * 0.70710678118654752f));
                    v2 = 0.5f * v2 * (1.f + erff(v2 * 0.70710678118654752f));
                    v3 = 0.5f * v3 * (1.f + erff(v3 * 0.70710678118654752f));
                }
            } else {
                const float2 ra = *(const float2*)(resid + (size_t)r0 * N + n);
                const float2 rb = *(const float2*)(resid + (size_t)r1 * N + n);
                v0 += c2v[ni * 2] + ra.x;  v1 += c2v[ni * 2 + 1] + ra.y;
                v2 += c2v[ni * 2] + rb.x;  v3 += c2v[ni * 2 + 1] + rb.y;
            }
            *(float2*)(C + (size_t)r0 * N + n) = make_float2(v0, v1);
            *(float2*)(C + (size_t)r1 * N + n) = make_float2(v2, v3);
        }
    }
}

// ---------------- attention over batch axis (len 8) per (s, head) -----------
#define QSTRIDE 1156
__global__ void __launch_bounds__(256) attn_k(const float* __restrict__ qkv,
                                              float* __restrict__ o) {
    __shared__ float sq[8 * QSTRIDE];
    __shared__ float sc[8][64];
    const int s   = blockIdx.x;
    const int tid = threadIdx.x;

#pragma unroll
    for (int j = 0; j < 9; ++j) {
        int i  = tid + j * 256;
        int b  = i / 288, jj = i % 288;
        float4 v = *(const float4*)(qkv + ((size_t)(b * Sq + s)) * NQKV + jj * 4);
        *(float4*)(sq + b * QSTRIDE + jj * 4) = v;
    }
    __syncthreads();

    const int h = tid >> 5, lane = tid & 31;
    const float scale = 0.14433756729740644f;   // 1/sqrt(48)

    {
        int idx0 = lane, idx1 = lane + 32;
        int b0 = idx0 >> 3, cc0 = idx0 & 7;
        int b1 = idx1 >> 3, cc1 = idx1 & 7;
        const float4* q0 = (const float4*)(sq + b0 * QSTRIDE + h * 48);
        const float4* k0 = (const float4*)(sq + cc0 * QSTRIDE + 384 + h * 48);
        const float4* q1 = (const float4*)(sq + b1 * QSTRIDE + h * 48);
        const float4* k1 = (const float4*)(sq + cc1 * QSTRIDE + 384 + h * 48);
        float s0 = 0.f, s1 = 0.f;
#pragma unroll
        for (int d4 = 0; d4 < 12; ++d4) {
            float4 qa = q0[d4], ka = k0[d4];
            s0 += qa.x * ka.x + qa.y * ka.y + qa.z * ka.z + qa.w * ka.w;
            float4 qb = q1[d4], kb = k1[d4];
            s1 += qb.x * kb.x + qb.y * kb.y + qb.z * kb.z + qb.w * kb.w;
        }
        sc[h][idx0] = s0 * scale;
        sc[h][idx1] = s1 * scale;
    }
    __syncwarp();

    if (lane < 8) {
        float e[8]; float mx = -1e30f;
#pragma unroll
        for (int c = 0; c < 8; ++c) { e[c] = sc[h][lane * 8 + c]; mx = fmaxf(mx, e[c]); }
        float sum = 0.f;
#pragma unroll
        for (int c = 0; c < 8; ++c) { e[c] = expf(e[c] - mx); sum += e[c]; }
        float inv = 1.f / sum;
#pragma unroll
        for (int c = 0; c < 8; ++c) sc[h][lane * 8 + c] = e[c] * inv;
    }
    __syncwarp();

#pragma unroll
    for (int j = 0; j < 3; ++j) {
        int e4 = lane + j * 32;
        int b = e4 / 12, d4 = e4 % 12;
        float4 acc = make_float4(0.f, 0.f, 0.f, 0.f);
#pragma unroll
        for (int c = 0; c < 8; ++c) {
            float p = sc[h][b * 8 + c];
            float4 v = *(const float4*)(sq + c * QSTRIDE + 768 + h * 48 + d4 * 4);
            acc.x += p * v.x; acc.y += p * v.y; acc.z += p * v.z; acc.w += p * v.w;
        }
        *(float4*)(o + ((size_t)(b * Sq + s)) * Eq + h * 48 + d4 * 4) = acc;
    }
}

// ---------------- launch -----------------------------------------------------
extern "C" void kernel_launch(void* const* d_in, const int* in_sizes, int n_in,
                              void* d_out, int out_size) {
    const float* x     = (const float*)d_in[0];
    const float* in_w  = (const float*)d_in[1];
    const float* in_b  = (const float*)d_in[2];
    const float* out_w = (const float*)d_in[3];
    const float* out_b = (const float*)d_in[4];
    const float* ln1g  = (const float*)d_in[5];
    const float* ln1b  = (const float*)d_in[6];
    const float* ln2g  = (const float*)d_in[7];
    const float* ln2b  = (const float*)d_in[8];
    const float* w1    = (const float*)d_in[9];
    const float* b1    = (const float*)d_in[10];
    const float* w2    = (const float*)d_in[11];
    const float* b2    = (const float*)d_in[12];
    float* out = (float*)d_out;

    float2* stats; float *qkv, *obuf, *x1, *hbuf, *wqkv, *w1p, *owp, *w2p;
    float *c1q, *c2q, *c1f, *c2f;
    cudaGetSymbolAddress((void**)&stats, g_stats);
    cudaGetSymbolAddress((void**)&qkv,   g_qkv);
    cudaGetSymbolAddress((void**)&obuf,  g_o);
    cudaGetSymbolAddress((void**)&x1,    g_x1);
    cudaGetSymbolAddress((void**)&hbuf,  g_h);
    cudaGetSymbolAddress((void**)&wqkv,  g_wqkv);
    cudaGetSymbolAddress((void**)&w1p,   g_w1p);
    cudaGetSymbolAddress((void**)&owp,   g_owp);
    cudaGetSymbolAddress((void**)&w2p,   g_w2p);
    cudaGetSymbolAddress((void**)&c1q,   g_c1q);
    cudaGetSymbolAddress((void**)&c2q,   g_c2q);
    cudaGetSymbolAddress((void**)&c1f,   g_c1f);
    cudaGetSymbolAddress((void**)&c2f,   g_c2f);

    cudaFuncSetAttribute(tc_gemm<0>, cudaFuncAttributeMaxDynamicSharedMemorySize, SMEM_GEMM);
    cudaFuncSetAttribute(tc_gemm<1>, cudaFuncAttributeMaxDynamicSharedMemorySize, SMEM_GEMM);
    cudaFuncSetAttribute(tc_gemm<2>, cudaFuncAttributeMaxDynamicSharedMemorySize, SMEM_GEMM);

    // 0) fold LN1 into in_proj weights; LN2 into w1; tf32-round out_w, w2
    prep_k<<<NQKV, 128>>>(in_w, in_b, ln1g, ln1b, wqkv, c1q, c2q, Eq);
    prep_k<<<FFq,  128>>>(w1,   b1,   ln2g, ln2b, w1p,  c1f, c2f, Eq);
    round_w_k<<<(Eq * Eq + 255) / 256, 256>>>(out_w, owp, Eq * Eq);
    round_w_k<<<(Eq * FFq + 255) / 256, 256>>>(w2, w2p, Eq * FFq);
    // 1) LN1 stats
    row_stats_k<<<MROWS / 8, 256>>>(x, stats);
    // 2) qkv = LN1(x) @ in_proj_w^T + in_proj_b   (LN folded)
    {
        dim3 g(NQKV / 128, MROWS / 128);
        tc_gemm<0><<<g, 256, SMEM_GEMM>>>(x, wqkv, nullptr, nullptr, stats,
                                          c1q, c2q, qkv, Eq, NQKV);
    }
    // 3) batch-axis attention per (s, head)
    attn_k<<<Sq, 256>>>(qkv, obuf);
    // 4) x1 = x + o @ out_w^T + out_b
    {
        dim3 g(Eq / 128, MROWS / 128);
        tc_gemm<2><<<g, 256, SMEM_GEMM>>>(obuf, owp, out_b, x, nullptr,
                                          nullptr, nullptr, x1, Eq, Eq);
    }
    // 5) LN2 stats
    row_stats_k<<<MROWS / 8, 256>>>(x1, stats);
    // 6) h = gelu( LN2(x1) @ w1^T + b1 )   (LN folded)
    {
        dim3 g(FFq / 128, MROWS / 128);
        tc_gemm<1><<<g, 256, SMEM_GEMM>>>(x1, w1p, nullptr, nullptr, stats,
                                          c1f, c2f, hbuf, Eq, FFq);
    }
    // 7) out = x1 + h @ w2^T + b2
    {
        dim3 g(Eq / 128, MROWS / 128);
        tc_gemm<2><<<g, 256, SMEM_GEMM>>>(hbuf, w2p, b2, x1, nullptr,
                                          nullptr, nullptr, out, FFq, Eq);
    }
}

// round 6
// speedup vs baseline: 2.4160x; 1.0475x over previous
#include <cuda_runtime.h>
#include <cstdint>
#include <math.h>

// Problem constants
#define Bq     8
#define Sq     16384          // 128*128
#define Eq     384
#define FFq    1536
#define MROWS  (Bq*Sq)        // 131072
#define EPSq   1e-5f
#define NQKV   1152

// ---------------- scratch (device globals; no allocation allowed) -----------
__device__ float2 g_stats[MROWS];
__device__ float  g_qkv[(size_t)MROWS * NQKV];   // 604 MB
__device__ float  g_o  [(size_t)MROWS * Eq];     // 201 MB
__device__ float  g_x1 [(size_t)MROWS * Eq];     // 201 MB
__device__ float  g_h  [(size_t)MROWS * FFq];    // 805 MB
__device__ float  g_wqkv[NQKV * Eq];             // g-scaled, tf32-rounded in_proj_w
__device__ float  g_w1p [FFq * Eq];              // g-scaled, tf32-rounded w1
__device__ float  g_owp [Eq * Eq];               // tf32-rounded out_w
__device__ float  g_w2p [Eq * FFq];              // tf32-rounded w2
__device__ float  g_c1q[NQKV], g_c2q[NQKV];
__device__ float  g_c1f[FFq],  g_c2f[FFq];

// ---------------- PTX helpers ------------------------------------------------
__device__ __forceinline__ uint32_t smem_u32(const void* p) {
    uint32_t a;
    asm("{ .reg .u64 t; cvta.to.shared.u64 t, %1; cvt.u32.u64 %0, t; }"
        : "=r"(a) : "l"(p));
    return a;
}
__device__ __forceinline__ void cp16(uint32_t s, const void* g) {
    asm volatile("cp.async.cg.shared.global [%0], [%1], 16;\n" :: "r"(s), "l"(g));
}
__device__ __forceinline__ void cp_commit() {
    asm volatile("cp.async.commit_group;\n" ::: "memory");
}
template<int N> __device__ __forceinline__ void cp_wait() {
    asm volatile("cp.async.wait_group %0;\n" :: "n"(N) : "memory");
}
__device__ __forceinline__ uint32_t cvt_tf32(float f) {
    uint32_t r;
    asm("cvt.rna.tf32.f32 %0, %1;" : "=r"(r) : "f"(f));
    return r;
}
__device__ __forceinline__ float tf32_round(float f) {
    return __uint_as_float(cvt_tf32(f));
}
__device__ __forceinline__ void mma_tf32(float* c, const uint32_t* a, const uint32_t* b) {
    asm volatile(
        "mma.sync.aligned.m16n8k8.row.col.f32.tf32.tf32.f32 "
        "{%0,%1,%2,%3}, {%4,%5,%6,%7}, {%8,%9}, {%0,%1,%2,%3};\n"
        : "+f"(c[0]), "+f"(c[1]), "+f"(c[2]), "+f"(c[3])
        : "r"(a[0]), "r"(a[1]), "r"(a[2]), "r"(a[3]), "r"(b[0]), "r"(b[1]));
}
__device__ __forceinline__ void ldsm_x4(uint32_t* r, uint32_t addr) {
    asm volatile("ldmatrix.sync.aligned.m8n8.x4.shared.b16 {%0,%1,%2,%3}, [%4];"
                 : "=r"(r[0]), "=r"(r[1]), "=r"(r[2]), "=r"(r[3]) : "r"(addr));
}

// ---------------- per-row mean/rstd (E = 384) -------------------------------
__global__ void __launch_bounds__(256) row_stats_k(const float* __restrict__ X,
                                                   float2* __restrict__ st) {
    int row  = blockIdx.x * 8 + (threadIdx.x >> 5);
    int lane = threadIdx.x & 31;
    const float4* x = (const float4*)(X + (size_t)row * Eq);
    float s = 0.f, ss = 0.f;
#pragma unroll
    for (int j = 0; j < 3; ++j) {
        float4 v = x[lane + 32 * j];
        s  += v.x + v.y + v.z + v.w;
        ss += v.x * v.x + v.y * v.y + v.z * v.z + v.w * v.w;
    }
#pragma unroll
    for (int o = 16; o; o >>= 1) {
        s  += __shfl_xor_sync(0xffffffffu, s,  o);
        ss += __shfl_xor_sync(0xffffffffu, ss, o);
    }
    if (lane == 0) {
        float m   = s * (1.f / Eq);
        float var = ss * (1.f / Eq) - m * m;
        st[row] = make_float2(m, rsqrtf(var + EPSq));
    }
}

// ---- LN fold prep: Wp = rnd_tf32(W*g), c1 = sum Wp, c2 = sum be*W + bias ----
__global__ void __launch_bounds__(128) prep_k(const float* __restrict__ W,
                                              const float* __restrict__ bias,
                                              const float* __restrict__ g,
                                              const float* __restrict__ be,
                                              float* __restrict__ Wp,
                                              float* __restrict__ c1,
                                              float* __restrict__ c2, int K) {
    int n = blockIdx.x, t = threadIdx.x;
    float s1 = 0.f, s2 = 0.f;
    for (int k = t; k < K; k += 128) {
        float w  = W[(size_t)n * K + k];
        float wp = tf32_round(w * g[k]);
        Wp[(size_t)n * K + k] = wp;
        s1 += wp;
        s2 += w * be[k];
    }
    __shared__ float r1[128], r2[128];
    r1[t] = s1; r2[t] = s2;
    __syncthreads();
    for (int o = 64; o; o >>= 1) {
        if (t < o) { r1[t] += r1[t + o]; r2[t] += r2[t + o]; }
        __syncthreads();
    }
    if (t == 0) { c1[n] = r1[0]; c2[n] = r2[0] + bias[n]; }
}

// ---- plain tf32 rounding of a weight matrix --------------------------------
__global__ void __launch_bounds__(256) round_w_k(const float* __restrict__ W,
                                                 float* __restrict__ Wp, int n) {
    int i = blockIdx.x * 256 + threadIdx.x;
    if (i < n) Wp[i] = tf32_round(W[i]);
}

// ---------------- tf32 mma.sync GEMM: C = A[M,K] @ W[N,K]^T (+epilogue) -----
// EPI 0: LN fold (r*acc - rm*c1 + c2)
// EPI 1: LN fold + erf-GELU
// EPI 2: + bias + residual
#define BKq      32
#define ASTRIDE  36                       // padded row stride (floats)
#define STAGE_F  (2 * 128 * ASTRIDE)      // A block + B block, floats
#define STAGE_B  (STAGE_F * 4)
#define SMEM_GEMM (2 * STAGE_B)           // double buffered, bytes

template<int EPI>
__global__ void __launch_bounds__(256, 2)
tc_gemm(const float* __restrict__ A, const float* __restrict__ W,
        const float* __restrict__ bias, const float* __restrict__ resid,
        const float2* __restrict__ stats, const float* __restrict__ c1,
        const float* __restrict__ c2, float* __restrict__ C, int K, int N)
{
    extern __shared__ float smemf[];
    const uint32_t sbase = smem_u32(smemf);
    const int tid = threadIdx.x;
    const int wid = tid >> 5, lane = tid & 31;
    const int g  = lane >> 2, tg = lane & 3;
    const int n0 = blockIdx.x * 128, m0 = blockIdx.y * 128;
    const int warp_m = wid >> 2, warp_n = wid & 3;       // 2 x 4 warp grid
    const int m_off = warp_m * 64, n_off = warp_n * 32;
    const int T = K / BKq;

    float acc[4][4][4];
#pragma unroll
    for (int mi = 0; mi < 4; ++mi)
#pragma unroll
        for (int ni = 0; ni < 4; ++ni)
#pragma unroll
            for (int j = 0; j < 4; ++j) acc[mi][ni][j] = 0.f;

    // ldmatrix per-lane base addresses (stage 0, k0 = 0)
    const int lr8 = lane & 7, q = lane >> 3;
    uint32_t baseA[4], baseB[2];
#pragma unroll
    for (int mi = 0; mi < 4; ++mi) {
        int row = m_off + mi * 16 + (q & 1) * 8 + lr8;
        int col = (q >> 1) * 4;
        baseA[mi] = sbase + (uint32_t)(row * ASTRIDE + col) * 4;
    }
#pragma unroll
    for (int p = 0; p < 2; ++p) {
        int row = n_off + (p * 2 + (q >> 1)) * 8 + lr8;
        int col = (q & 1) * 4;
        baseB[p] = sbase + (uint32_t)(128 * ASTRIDE + row * ASTRIDE + col) * 4;
    }

    // global-load setup: row = tid>>1, half = tid&1 covers 16 floats (4 x cp16)
    const int lr = tid >> 1, lh = tid & 1;
    const char* Ag = (const char*)(A + (size_t)(m0 + lr) * K + lh * 16);
    const char* Bg = (const char*)(W + (size_t)(n0 + lr) * K + lh * 16);
    const uint32_t dA = sbase + (uint32_t)(lr * ASTRIDE + lh * 16) * 4;
    const uint32_t dB = dA + 128 * ASTRIDE * 4;

    auto loadStage = [&](int buf, int kt) {
        const uint32_t so = (uint32_t)buf * STAGE_B;
        const char* ga = Ag + (size_t)kt * BKq * 4;
        const char* gb = Bg + (size_t)kt * BKq * 4;
#pragma unroll
        for (int c = 0; c < 4; ++c) {
            cp16(dA + so + c * 16, ga + c * 16);
            cp16(dB + so + c * 16, gb + c * 16);
        }
    };

    loadStage(0, 0); cp_commit();

    int cur = 0;
    for (int t = 0; t < T; ++t) {
        if (t + 1 < T) loadStage(cur ^ 1, t + 1);
        cp_commit();
        cp_wait<1>();
        __syncthreads();

        const uint32_t so = (uint32_t)cur * STAGE_B;
#pragma unroll
        for (int ks = 0; ks < 4; ++ks) {
            const uint32_t ko = so + ks * 32;          // 8 floats per k-step
            uint32_t a[4][4], b[4][2], tb[4];
#pragma unroll
            for (int mi = 0; mi < 4; ++mi) {
                ldsm_x4(a[mi], baseA[mi] + ko);
#pragma unroll
                for (int j = 0; j < 4; ++j)
                    a[mi][j] = cvt_tf32(__uint_as_float(a[mi][j]));
            }
            ldsm_x4(tb, baseB[0] + ko);
            b[0][0] = tb[0]; b[0][1] = tb[1]; b[1][0] = tb[2]; b[1][1] = tb[3];
            ldsm_x4(tb, baseB[1] + ko);
            b[2][0] = tb[0]; b[2][1] = tb[1]; b[3][0] = tb[2]; b[3][1] = tb[3];
#pragma unroll
            for (int mi = 0; mi < 4; ++mi)
#pragma unroll
                for (int ni = 0; ni < 4; ++ni)
                    mma_tf32(acc[mi][ni], a[mi], b[ni]);
        }
        __syncthreads();
        cur ^= 1;
    }

    // ---------------- epilogue ----------------
    // acc[mi][ni]: rows m0+m_off+mi*16+{g, g+8}, cols n0+n_off+ni*8+2tg+{0,1}
    float c1v[8], c2v[8];
    if (EPI != 2) {
#pragma unroll
        for (int ni = 0; ni < 4; ++ni) {
            int n = n0 + n_off + ni * 8 + 2 * tg;
            c1v[ni * 2]     = c1[n];     c2v[ni * 2]     = c2[n];
            c1v[ni * 2 + 1] = c1[n + 1]; c2v[ni * 2 + 1] = c2[n + 1];
        }
    } else {
#pragma unroll
        for (int ni = 0; ni < 4; ++ni) {
            int n = n0 + n_off + ni * 8 + 2 * tg;
            c2v[ni * 2]     = bias[n];
            c2v[ni * 2 + 1] = bias[n + 1];
        }
    }

#pragma unroll
    for (int mi = 0; mi < 4; ++mi) {
        const int r0 = m0 + m_off + mi * 16 + g;
        const int r1 = r0 + 8;
        float rr0 = 0.f, rm0 = 0.f, rr1 = 0.f, rm1 = 0.f;
        if (EPI != 2) {
            float2 s0 = stats[r0], s1 = stats[r1];
            rr0 = s0.y; rm0 = s0.x * s0.y;
            rr1 = s1.y; rm1 = s1.x * s1.y;
        }
#pragma unroll
        for (int ni = 0; ni < 4; ++ni) {
            const int n = n0 + n_off + ni * 8 + 2 * tg;
            float v0 = acc[mi][ni][0], v1 = acc[mi][ni][1];
            float v2 = acc[mi][ni][2], v3 = acc[mi][ni][3];
            if (EPI == 0 || EPI == 1) {
                v0 = rr0 * v0 - rm0 * c1v[ni * 2]     + c2v[ni * 2];
                v1 = rr0 * v1 - rm0 * c1v[ni * 2 + 1] + c2v[ni * 2 + 1];
                v2 = rr1 * v2 - rm1 * c1v[ni * 2]     + c2v[ni * 2];
                v3 = rr1 * v3 - rm1 * c1v[ni * 2 + 1] + c2v[ni * 2 + 1];
                if (EPI == 1) {
                    v0 = 0.5f * v0 * (1.f + erff(v0 * 0.70710678118654752f));
                    v1 = 0.5f * v1 * (1.f + erff(v1 * 0.70710678118654752f));
                    v2 = 0.5f * v2 * (1.f + erff(v2 * 0.70710678118654752f));
                    v3 = 0.5f * v3 * (1.f + erff(v3 * 0.70710678118654752f));
                }
            } else {
                const float2 ra = *(const float2*)(resid + (size_t)r0 * N + n);
                const float2 rb = *(const float2*)(resid + (size_t)r1 * N + n);
                v0 += c2v[ni * 2] + ra.x;  v1 += c2v[ni * 2 + 1] + ra.y;
                v2 += c2v[ni * 2] + rb.x;  v3 += c2v[ni * 2 + 1] + rb.y;
            }
            *(float2*)(C + (size_t)r0 * N + n) = make_float2(v0, v1);
            *(float2*)(C + (size_t)r1 * N + n) = make_float2(v2, v3);
        }
    }
}

// ---------------- attention over batch axis (len 8) per (s, head) -----------
#define QSTRIDE 1156
__global__ void __launch_bounds__(256) attn_k(const float* __restrict__ qkv,
                                              float* __restrict__ o) {
    __shared__ float sq[8 * QSTRIDE];
    __shared__ float sc[8][64];
    const int s   = blockIdx.x;
    const int tid = threadIdx.x;

#pragma unroll
    for (int j = 0; j < 9; ++j) {
        int i  = tid + j * 256;
        int b  = i / 288, jj = i % 288;
        float4 v = *(const float4*)(qkv + ((size_t)(b * Sq + s)) * NQKV + jj * 4);
        *(float4*)(sq + b * QSTRIDE + jj * 4) = v;
    }
    __syncthreads();

    const int h = tid >> 5, lane = tid & 31;
    const float scale = 0.14433756729740644f;   // 1/sqrt(48)

    {
        int idx0 = lane, idx1 = lane + 32;
        int b0 = idx0 >> 3, cc0 = idx0 & 7;
        int b1 = idx1 >> 3, cc1 = idx1 & 7;
        const float4* q0 = (const float4*)(sq + b0 * QSTRIDE + h * 48);
        const float4* k0 = (const float4*)(sq + cc0 * QSTRIDE + 384 + h * 48);
        const float4* q1 = (const float4*)(sq + b1 * QSTRIDE + h * 48);
        const float4* k1 = (const float4*)(sq + cc1 * QSTRIDE + 384 + h * 48);
        float s0 = 0.f, s1 = 0.f;
#pragma unroll
        for (int d4 = 0; d4 < 12; ++d4) {
            float4 qa = q0[d4], ka = k0[d4];
            s0 += qa.x * ka.x + qa.y * ka.y + qa.z * ka.z + qa.w * ka.w;
            float4 qb = q1[d4], kb = k1[d4];
            s1 += qb.x * kb.x + qb.y * kb.y + qb.z * kb.z + qb.w * kb.w;
        }
        sc[h][idx0] = s0 * scale;
        sc[h][idx1] = s1 * scale;
    }
    __syncwarp();

    if (lane < 8) {
        float e[8]; float mx = -1e30f;
#pragma unroll
        for (int c = 0; c < 8; ++c) { e[c] = sc[h][lane * 8 + c]; mx = fmaxf(mx, e[c]); }
        float sum = 0.f;
#pragma unroll
        for (int c = 0; c < 8; ++c) { e[c] = expf(e[c] - mx); sum += e[c]; }
        float inv = 1.f / sum;
#pragma unroll
        for (int c = 0; c < 8; ++c) sc[h][lane * 8 + c] = e[c] * inv;
    }
    __syncwarp();

#pragma unroll
    for (int j = 0; j < 3; ++j) {
        int e4 = lane + j * 32;
        int b = e4 / 12, d4 = e4 % 12;
        float4 acc = make_float4(0.f, 0.f, 0.f, 0.f);
#pragma unroll
        for (int c = 0; c < 8; ++c) {
            float p = sc[h][b * 8 + c];
            float4 v = *(const float4*)(sq + c * QSTRIDE + 768 + h * 48 + d4 * 4);
            acc.x += p * v.x; acc.y += p * v.y; acc.z += p * v.z; acc.w += p * v.w;
        }
        *(float4*)(o + ((size_t)(b * Sq + s)) * Eq + h * 48 + d4 * 4) = acc;
    }
}

// ---------------- launch -----------------------------------------------------
extern "C" void kernel_launch(void* const* d_in, const int* in_sizes, int n_in,
                              void* d_out, int out_size) {
    const float* x     = (const float*)d_in[0];
    const float* in_w  = (const float*)d_in[1];
    const float* in_b  = (const float*)d_in[2];
    const float* out_w = (const float*)d_in[3];
    const float* out_b = (const float*)d_in[4];
    const float* ln1g  = (const float*)d_in[5];
    const float* ln1b  = (const float*)d_in[6];
    const float* ln2g  = (const float*)d_in[7];
    const float* ln2b  = (const float*)d_in[8];
    const float* w1    = (const float*)d_in[9];
    const float* b1    = (const float*)d_in[10];
    const float* w2    = (const float*)d_in[11];
    const float* b2    = (const float*)d_in[12];
    float* out = (float*)d_out;

    float2* stats; float *qkv, *obuf, *x1, *hbuf, *wqkv, *w1p, *owp, *w2p;
    float *c1q, *c2q, *c1f, *c2f;
    cudaGetSymbolAddress((void**)&stats, g_stats);
    cudaGetSymbolAddress((void**)&qkv,   g_qkv);
    cudaGetSymbolAddress((void**)&obuf,  g_o);
    cudaGetSymbolAddress((void**)&x1,    g_x1);
    cudaGetSymbolAddress((void**)&hbuf,  g_h);
    cudaGetSymbolAddress((void**)&wqkv,  g_wqkv);
    cudaGetSymbolAddress((void**)&w1p,   g_w1p);
    cudaGetSymbolAddress((void**)&owp,   g_owp);
    cudaGetSymbolAddress((void**)&w2p,   g_w2p);
    cudaGetSymbolAddress((void**)&c1q,   g_c1q);
    cudaGetSymbolAddress((void**)&c2q,   g_c2q);
    cudaGetSymbolAddress((void**)&c1f,   g_c1f);
    cudaGetSymbolAddress((void**)&c2f,   g_c2f);

    cudaFuncSetAttribute(tc_gemm<0>, cudaFuncAttributeMaxDynamicSharedMemorySize, SMEM_GEMM);
    cudaFuncSetAttribute(tc_gemm<1>, cudaFuncAttributeMaxDynamicSharedMemorySize, SMEM_GEMM);
    cudaFuncSetAttribute(tc_gemm<2>, cudaFuncAttributeMaxDynamicSharedMemorySize, SMEM_GEMM);

    // 0) fold LN1 into in_proj weights; LN2 into w1; tf32-round out_w, w2
    prep_k<<<NQKV, 128>>>(in_w, in_b, ln1g, ln1b, wqkv, c1q, c2q, Eq);
    prep_k<<<FFq,  128>>>(w1,   b1,   ln2g, ln2b, w1p,  c1f, c2f, Eq);
    round_w_k<<<(Eq * Eq + 255) / 256, 256>>>(out_w, owp, Eq * Eq);
    round_w_k<<<(Eq * FFq + 255) / 256, 256>>>(w2, w2p, Eq * FFq);
    // 1) LN1 stats
    row_stats_k<<<MROWS / 8, 256>>>(x, stats);
    // 2) qkv = LN1(x) @ in_proj_w^T + in_proj_b   (LN folded)
    {
        dim3 g(NQKV / 128, MROWS / 128);
        tc_gemm<0><<<g, 256, SMEM_GEMM>>>(x, wqkv, nullptr, nullptr, stats,
                                          c1q, c2q, qkv, Eq, NQKV);
    }
    // 3) batch-axis attention per (s, head)
    attn_k<<<Sq, 256>>>(qkv, obuf);
    // 4) x1 = x + o @ out_w^T + out_b
    {
        dim3 g(Eq / 128, MROWS / 128);
        tc_gemm<2><<<g, 256, SMEM_GEMM>>>(obuf, owp, out_b, x, nullptr,
                                          nullptr, nullptr, x1, Eq, Eq);
    }
    // 5) LN2 stats
    row_stats_k<<<MROWS / 8, 256>>>(x1, stats);
    // 6) h = gelu( LN2(x1) @ w1^T + b1 )   (LN folded)
    {
        dim3 g(FFq / 128, MROWS / 128);
        tc_gemm<1><<<g, 256, SMEM_GEMM>>>(x1, w1p, nullptr, nullptr, stats,
                                          c1f, c2f, hbuf, Eq, FFq);
    }
    // 7) out = x1 + h @ w2^T + b2
    {
        dim3 g(Eq / 128, MROWS / 128);
        tc_gemm<2><<<g, 256, SMEM_GEMM>>>(hbuf, w2p, b2, x1, nullptr,
                                          nullptr, nullptr, out, FFq, Eq);
    }
}

// round 7
// speedup vs baseline: 4.5621x; 1.8883x over previous
#include <cuda_runtime.h>
#include <cuda_fp16.h>
#include <cstdint>
#include <math.h>

// Problem constants
#define Bq     8
#define Sq     16384          // 128*128
#define Eq     384
#define FFq    1536
#define MROWS  (Bq*Sq)        // 131072
#define EPSq   1e-5f
#define NQKV   1152

// ---------------- scratch (device globals; no allocation allowed) -----------
__device__ float2 g_stats[MROWS];
__device__ __half g_xh [(size_t)MROWS * Eq];     // fp16 copy of x (GEMM A)
__device__ __half g_qkv[(size_t)MROWS * NQKV];   // 302 MB
__device__ __half g_o  [(size_t)MROWS * Eq];     // 100 MB
__device__ float  g_x1 [(size_t)MROWS * Eq];     // fp32 residual stream
__device__ __half g_x1h[(size_t)MROWS * Eq];     // fp16 copy for FF1 A
__device__ __half g_h  [(size_t)MROWS * FFq];    // 402 MB
__device__ __half g_wqkv[NQKV * Eq];             // g-scaled fp16 in_proj_w
__device__ __half g_w1p [FFq * Eq];              // g-scaled fp16 w1
__device__ __half g_owp [Eq * Eq];               // fp16 out_w
__device__ __half g_w2p [Eq * FFq];              // fp16 w2
__device__ float  g_c1q[NQKV], g_c2q[NQKV];
__device__ float  g_c1f[FFq],  g_c2f[FFq];

// ---------------- PTX helpers ------------------------------------------------
__device__ __forceinline__ uint32_t smem_u32(const void* p) {
    uint32_t a;
    asm("{ .reg .u64 t; cvta.to.shared.u64 t, %1; cvt.u32.u64 %0, t; }"
        : "=r"(a) : "l"(p));
    return a;
}
__device__ __forceinline__ void cp16(uint32_t s, const void* g) {
    asm volatile("cp.async.cg.shared.global [%0], [%1], 16;\n" :: "r"(s), "l"(g));
}
__device__ __forceinline__ void cp_commit() {
    asm volatile("cp.async.commit_group;\n" ::: "memory");
}
template<int N> __device__ __forceinline__ void cp_wait() {
    asm volatile("cp.async.wait_group %0;\n" :: "n"(N) : "memory");
}
// fp16 mma m16n8k16, f32 accumulate
__device__ __forceinline__ void mma_f16(float* c, const uint32_t* a, const uint32_t* b) {
    asm volatile(
        "mma.sync.aligned.m16n8k16.row.col.f32.f16.f16.f32 "
        "{%0,%1,%2,%3}, {%4,%5,%6,%7}, {%8,%9}, {%0,%1,%2,%3};\n"
        : "+f"(c[0]), "+f"(c[1]), "+f"(c[2]), "+f"(c[3])
        : "r"(a[0]), "r"(a[1]), "r"(a[2]), "r"(a[3]), "r"(b[0]), "r"(b[1]));
}
__device__ __forceinline__ void ldsm_x4(uint32_t* r, uint32_t addr) {
    asm volatile("ldmatrix.sync.aligned.m8n8.x4.shared.b16 {%0,%1,%2,%3}, [%4];"
                 : "=r"(r[0]), "=r"(r[1]), "=r"(r[2]), "=r"(r[3]) : "r"(addr));
}

// ---------------- per-row mean/rstd (E = 384, fp32 input) --------------------
__global__ void __launch_bounds__(256) row_stats_k(const float* __restrict__ X,
                                                   float2* __restrict__ st) {
    int row  = blockIdx.x * 8 + (threadIdx.x >> 5);
    int lane = threadIdx.x & 31;
    const float4* x = (const float4*)(X + (size_t)row * Eq);
    float s = 0.f, ss = 0.f;
#pragma unroll
    for (int j = 0; j < 3; ++j) {
        float4 v = x[lane + 32 * j];
        s  += v.x + v.y + v.z + v.w;
        ss += v.x * v.x + v.y * v.y + v.z * v.z + v.w * v.w;
    }
#pragma unroll
    for (int o = 16; o; o >>= 1) {
        s  += __shfl_xor_sync(0xffffffffu, s,  o);
        ss += __shfl_xor_sync(0xffffffffu, ss, o);
    }
    if (lane == 0) {
        float m   = s * (1.f / Eq);
        float var = ss * (1.f / Eq) - m * m;
        st[row] = make_float2(m, rsqrtf(var + EPSq));
    }
}

// ---- LN fold prep: Wp = fp16(W*g), c1 = sum Wp, c2 = sum be*W + bias --------
__global__ void __launch_bounds__(128) prep_k(const float* __restrict__ W,
                                              const float* __restrict__ bias,
                                              const float* __restrict__ g,
                                              const float* __restrict__ be,
                                              __half* __restrict__ Wp,
                                              float* __restrict__ c1,
                                              float* __restrict__ c2, int K) {
    int n = blockIdx.x, t = threadIdx.x;
    float s1 = 0.f, s2 = 0.f;
    for (int k = t; k < K; k += 128) {
        float w  = W[(size_t)n * K + k];
        __half hp = __float2half_rn(w * g[k]);
        Wp[(size_t)n * K + k] = hp;
        s1 += __half2float(hp);
        s2 += w * be[k];
    }
    __shared__ float r1[128], r2[128];
    r1[t] = s1; r2[t] = s2;
    __syncthreads();
    for (int o = 64; o; o >>= 1) {
        if (t < o) { r1[t] += r1[t + o]; r2[t] += r2[t + o]; }
        __syncthreads();
    }
    if (t == 0) { c1[n] = r1[0]; c2[n] = r2[0] + bias[n]; }
}

// ---- fp16 conversion of a float array ---------------------------------------
__global__ void __launch_bounds__(256) cvt_h_k(const float* __restrict__ W,
                                               __half* __restrict__ Wp, int n) {
    int i = blockIdx.x * 256 + threadIdx.x;
    if (i < n) Wp[i] = __float2half_rn(W[i]);
}

// ---------------- fp16 mma.sync GEMM: C = A[M,K] @ W[N,K]^T (+epilogue) -----
// EPI 0: LN fold (r*acc - rm*c1 + c2)
// EPI 1: LN fold + erf-GELU
// EPI 2: + bias + residual
// WH: also write __half output Ch; WF: write float output Cf
#define BKq      32
#define ASTRIDE  40                        // halves; 80B row stride, 16B aligned
#define STAGE_H  (2 * 128 * ASTRIDE)       // A + B halves per stage
#define STAGE_B  (STAGE_H * 2)             // bytes (20480)
#define SMEM_GEMM (2 * STAGE_B)            // double buffered (40960 B)

template<int EPI, bool WH, bool WF>
__global__ void __launch_bounds__(256, 2)
tc_gemm(const __half* __restrict__ A, const __half* __restrict__ W,
        const float* __restrict__ bias, const float* __restrict__ resid,
        const float2* __restrict__ stats, const float* __restrict__ c1,
        const float* __restrict__ c2, float* __restrict__ Cf,
        __half* __restrict__ Ch, int K, int N)
{
    extern __shared__ __half smemh[];
    const uint32_t sbase = smem_u32(smemh);
    const int tid = threadIdx.x;
    const int wid = tid >> 5, lane = tid & 31;
    const int g  = lane >> 2, tg = lane & 3;
    const int n0 = blockIdx.x * 128, m0 = blockIdx.y * 128;
    const int warp_m = wid >> 2, warp_n = wid & 3;       // 2 x 4 warp grid
    const int m_off = warp_m * 64, n_off = warp_n * 32;
    const int T = K / BKq;

    float acc[4][4][4];
#pragma unroll
    for (int mi = 0; mi < 4; ++mi)
#pragma unroll
        for (int ni = 0; ni < 4; ++ni)
#pragma unroll
            for (int j = 0; j < 4; ++j) acc[mi][ni][j] = 0.f;

    // ldmatrix per-lane base addresses (stage 0, k = 0); byte offsets
    const int lr8 = lane & 7;
    uint32_t baseA[4], baseB[2];
#pragma unroll
    for (int mi = 0; mi < 4; ++mi) {
        int row  = m_off + mi * 16 + ((lane >> 3) & 1) * 8 + lr8;
        int colh = (lane >> 4) * 8;
        baseA[mi] = sbase + (uint32_t)(row * ASTRIDE + colh) * 2;
    }
#pragma unroll
    for (int p = 0; p < 2; ++p) {
        int row  = n_off + p * 16 + ((lane >> 4) & 1) * 8 + lr8;
        int colh = ((lane >> 3) & 1) * 8;
        baseB[p] = sbase + (uint32_t)((128 + row) * ASTRIDE + colh) * 2;
    }

    // global loads: row = tid>>1 (0..127), half = tid&1 -> 2 x 16B chunks each
    const int lr = tid >> 1, lh = tid & 1;
    const char* Ag = (const char*)(A + (size_t)(m0 + lr) * K) + lh * 32;
    const char* Bg = (const char*)(W + (size_t)(n0 + lr) * K) + lh * 32;
    const uint32_t dA = sbase + (uint32_t)(lr * ASTRIDE) * 2 + lh * 32;
    const uint32_t dB = dA + 128 * ASTRIDE * 2;

    auto loadStage = [&](int buf, int kt) {
        const uint32_t so = (uint32_t)buf * STAGE_B;
        const char* ga = Ag + (size_t)kt * (BKq * 2);     // 64 bytes per k-tile
        const char* gb = Bg + (size_t)kt * (BKq * 2);
#pragma unroll
        for (int c = 0; c < 2; ++c) {
            cp16(dA + so + c * 16, ga + c * 16);
            cp16(dB + so + c * 16, gb + c * 16);
        }
    };

    loadStage(0, 0); cp_commit();

    int cur = 0;
    for (int t = 0; t < T; ++t) {
        if (t + 1 < T) loadStage(cur ^ 1, t + 1);
        cp_commit();
        cp_wait<1>();
        __syncthreads();

        const uint32_t so = (uint32_t)cur * STAGE_B;
#pragma unroll
        for (int ks = 0; ks < 2; ++ks) {
            const uint32_t ko = so + ks * 32;             // 16 halves = 32 bytes
            uint32_t a[4][4], b[4][2], tb[4];
#pragma unroll
            for (int mi = 0; mi < 4; ++mi)
                ldsm_x4(a[mi], baseA[mi] + ko);
#pragma unroll
            for (int p = 0; p < 2; ++p) {
                ldsm_x4(tb, baseB[p] + ko);
                b[2*p][0]   = tb[0]; b[2*p][1]   = tb[1];
                b[2*p+1][0] = tb[2]; b[2*p+1][1] = tb[3];
            }
#pragma unroll
            for (int mi = 0; mi < 4; ++mi)
#pragma unroll
                for (int ni = 0; ni < 4; ++ni)
                    mma_f16(acc[mi][ni], a[mi], b[ni]);
        }
        __syncthreads();
        cur ^= 1;
    }

    // ---------------- epilogue ----------------
    // acc[mi][ni]: rows m0+m_off+mi*16+{g, g+8}, cols n0+n_off+ni*8+2tg+{0,1}
    float c1v[8], c2v[8];
#pragma unroll
    for (int ni = 0; ni < 4; ++ni) {
        int n = n0 + n_off + ni * 8 + 2 * tg;
        if (EPI != 2) {
            c1v[ni * 2]     = c1[n];     c2v[ni * 2]     = c2[n];
            c1v[ni * 2 + 1] = c1[n + 1]; c2v[ni * 2 + 1] = c2[n + 1];
        } else {
            c2v[ni * 2]     = bias[n];
            c2v[ni * 2 + 1] = bias[n + 1];
        }
    }

#pragma unroll
    for (int mi = 0; mi < 4; ++mi) {
        const int r0 = m0 + m_off + mi * 16 + g;
        const int r1 = r0 + 8;
        float rr0 = 0.f, rm0 = 0.f, rr1 = 0.f, rm1 = 0.f;
        if (EPI != 2) {
            float2 s0 = stats[r0], s1 = stats[r1];
            rr0 = s0.y; rm0 = s0.x * s0.y;
            rr1 = s1.y; rm1 = s1.x * s1.y;
        }
#pragma unroll
        for (int ni = 0; ni < 4; ++ni) {
            const int n = n0 + n_off + ni * 8 + 2 * tg;
            float v0 = acc[mi][ni][0], v1 = acc[mi][ni][1];
            float v2 = acc[mi][ni][2], v3 = acc[mi][ni][3];
            if (EPI == 0 || EPI == 1) {
                v0 = rr0 * v0 - rm0 * c1v[ni * 2]     + c2v[ni * 2];
                v1 = rr0 * v1 - rm0 * c1v[ni * 2 + 1] + c2v[ni * 2 + 1];
                v2 = rr1 * v2 - rm1 * c1v[ni * 2]     + c2v[ni * 2];
                v3 = rr1 * v3 - rm1 * c1v[ni * 2 + 1] + c2v[ni * 2 + 1];
                if (EPI == 1) {
                    v0 = 0.5f * v0 * (1.f + erff(v0 * 0.70710678118654752f));
                    v1 = 0.5f * v1 * (1.f + erff(v1 * 0.70710678118654752f));
                    v2 = 0.5f * v2 * (1.f + erff(v2 * 0.70710678118654752f));
                    v3 = 0.5f * v3 * (1.f + erff(v3 * 0.70710678118654752f));
                }
            } else {
                const float2 ra = *(const float2*)(resid + (size_t)r0 * N + n);
                const float2 rb = *(const float2*)(resid + (size_t)r1 * N + n);
                v0 += c2v[ni * 2] + ra.x;  v1 += c2v[ni * 2 + 1] + ra.y;
                v2 += c2v[ni * 2] + rb.x;  v3 += c2v[ni * 2 + 1] + rb.y;
            }
            if (WF) {
                *(float2*)(Cf + (size_t)r0 * N + n) = make_float2(v0, v1);
                *(float2*)(Cf + (size_t)r1 * N + n) = make_float2(v2, v3);
            }
            if (WH) {
                *(__half2*)(Ch + (size_t)r0 * N + n) = __floats2half2_rn(v0, v1);
                *(__half2*)(Ch + (size_t)r1 * N + n) = __floats2half2_rn(v2, v3);
            }
        }
    }
}

// ---------------- attention over batch axis (len 8) per (s, head) -----------
#define QSTRIDE 1156
__global__ void __launch_bounds__(256) attn_k(const __half* __restrict__ qkv,
                                              __half* __restrict__ o) {
    __shared__ float sq[8 * QSTRIDE];
    __shared__ float sc[8][64];
    const int s   = blockIdx.x;
    const int tid = threadIdx.x;

#pragma unroll
    for (int j = 0; j < 5; ++j) {            // 8 rows x 144 uint4 = 1152 loads
        int i = tid + j * 256;
        if (i < 1152) {
            int b = i / 144, jj = i % 144;
            uint4 v = *(const uint4*)(qkv + ((size_t)(b * Sq + s)) * NQKV + jj * 8);
            const __half2* h2 = (const __half2*)&v;
            float* dst = sq + b * QSTRIDE + jj * 8;
            float2 f0 = __half22float2(h2[0]);
            float2 f1 = __half22float2(h2[1]);
            float2 f2 = __half22float2(h2[2]);
            float2 f3 = __half22float2(h2[3]);
            *(float4*)(dst)     = make_float4(f0.x, f0.y, f1.x, f1.y);
            *(float4*)(dst + 4) = make_float4(f2.x, f2.y, f3.x, f3.y);
        }
    }
    __syncthreads();

    const int h = tid >> 5, lane = tid & 31;
    const float scale = 0.14433756729740644f;   // 1/sqrt(48)

    {
        int idx0 = lane, idx1 = lane + 32;
        int b0 = idx0 >> 3, cc0 = idx0 & 7;
        int b1 = idx1 >> 3, cc1 = idx1 & 7;
        const float4* q0 = (const float4*)(sq + b0 * QSTRIDE + h * 48);
        const float4* k0 = (const float4*)(sq + cc0 * QSTRIDE + 384 + h * 48);
        const float4* q1 = (const float4*)(sq + b1 * QSTRIDE + h * 48);
        const float4* k1 = (const float4*)(sq + cc1 * QSTRIDE + 384 + h * 48);
        float s0 = 0.f, s1 = 0.f;
#pragma unroll
        for (int d4 = 0; d4 < 12; ++d4) {
            float4 qa = q0[d4], ka = k0[d4];
            s0 += qa.x * ka.x + qa.y * ka.y + qa.z * ka.z + qa.w * ka.w;
            float4 qb = q1[d4], kb = k1[d4];
            s1 += qb.x * kb.x + qb.y * kb.y + qb.z * kb.z + qb.w * kb.w;
        }
        sc[h][idx0] = s0 * scale;
        sc[h][idx1] = s1 * scale;
    }
    __syncwarp();

    if (lane < 8) {
        float e[8]; float mx = -1e30f;
#pragma unroll
        for (int c = 0; c < 8; ++c) { e[c] = sc[h][lane * 8 + c]; mx = fmaxf(mx, e[c]); }
        float sum = 0.f;
#pragma unroll
        for (int c = 0; c < 8; ++c) { e[c] = expf(e[c] - mx); sum += e[c]; }
        float inv = 1.f / sum;
#pragma unroll
        for (int c = 0; c < 8; ++c) sc[h][lane * 8 + c] = e[c] * inv;
    }
    __syncwarp();

#pragma unroll
    for (int j = 0; j < 3; ++j) {
        int e4 = lane + j * 32;
        int b = e4 / 12, d4 = e4 % 12;
        float4 acc = make_float4(0.f, 0.f, 0.f, 0.f);
#pragma unroll
        for (int c = 0; c < 8; ++c) {
            float p = sc[h][b * 8 + c];
            float4 v = *(const float4*)(sq + c * QSTRIDE + 768 + h * 48 + d4 * 4);
            acc.x += p * v.x; acc.y += p * v.y; acc.z += p * v.z; acc.w += p * v.w;
        }
        __half2 o0 = __floats2half2_rn(acc.x, acc.y);
        __half2 o1 = __floats2half2_rn(acc.z, acc.w);
        __half2* dst = (__half2*)(o + ((size_t)(b * Sq + s)) * Eq + h * 48 + d4 * 4);
        dst[0] = o0; dst[1] = o1;
    }
}

// ---------------- launch -----------------------------------------------------
extern "C" void kernel_launch(void* const* d_in, const int* in_sizes, int n_in,
                              void* d_out, int out_size) {
    const float* x     = (const float*)d_in[0];
    const float* in_w  = (const float*)d_in[1];
    const float* in_b  = (const float*)d_in[2];
    const float* out_w = (const float*)d_in[3];
    const float* out_b = (const float*)d_in[4];
    const float* ln1g  = (const float*)d_in[5];
    const float* ln1b  = (const float*)d_in[6];
    const float* ln2g  = (const float*)d_in[7];
    const float* ln2b  = (const float*)d_in[8];
    const float* w1    = (const float*)d_in[9];
    const float* b1    = (const float*)d_in[10];
    const float* w2    = (const float*)d_in[11];
    const float* b2    = (const float*)d_in[12];
    float* out = (float*)d_out;

    float2* stats; float *x1, *c1q, *c2q, *c1f, *c2f;
    __half *xh, *qkv, *obuf, *x1h, *hbuf, *wqkv, *w1p, *owp, *w2p;
    cudaGetSymbolAddress((void**)&stats, g_stats);
    cudaGetSymbolAddress((void**)&xh,    g_xh);
    cudaGetSymbolAddress((void**)&qkv,   g_qkv);
    cudaGetSymbolAddress((void**)&obuf,  g_o);
    cudaGetSymbolAddress((void**)&x1,    g_x1);
    cudaGetSymbolAddress((void**)&x1h,   g_x1h);
    cudaGetSymbolAddress((void**)&hbuf,  g_h);
    cudaGetSymbolAddress((void**)&wqkv,  g_wqkv);
    cudaGetSymbolAddress((void**)&w1p,   g_w1p);
    cudaGetSymbolAddress((void**)&owp,   g_owp);
    cudaGetSymbolAddress((void**)&w2p,   g_w2p);
    cudaGetSymbolAddress((void**)&c1q,   g_c1q);
    cudaGetSymbolAddress((void**)&c2q,   g_c2q);
    cudaGetSymbolAddress((void**)&c1f,   g_c1f);
    cudaGetSymbolAddress((void**)&c2f,   g_c2f);

    cudaFuncSetAttribute((const void*)tc_gemm<0, true, false>,
                         cudaFuncAttributeMaxDynamicSharedMemorySize, SMEM_GEMM);
    cudaFuncSetAttribute((const void*)tc_gemm<1, true, false>,
                         cudaFuncAttributeMaxDynamicSharedMemorySize, SMEM_GEMM);
    cudaFuncSetAttribute((const void*)tc_gemm<2, true, true>,
                         cudaFuncAttributeMaxDynamicSharedMemorySize, SMEM_GEMM);
    cudaFuncSetAttribute((const void*)tc_gemm<2, false, true>,
                         cudaFuncAttributeMaxDynamicSharedMemorySize, SMEM_GEMM);

    // 0) fold LN1 into in_proj weights; LN2 into w1; fp16-convert out_w, w2, x
    prep_k<<<NQKV, 128>>>(in_w, in_b, ln1g, ln1b, wqkv, c1q, c2q, Eq);
    prep_k<<<FFq,  128>>>(w1,   b1,   ln2g, ln2b, w1p,  c1f, c2f, Eq);
    cvt_h_k<<<(Eq * Eq + 255) / 256, 256>>>(out_w, owp, Eq * Eq);
    cvt_h_k<<<(Eq * FFq + 255) / 256, 256>>>(w2, w2p, Eq * FFq);
    cvt_h_k<<<(MROWS * Eq + 255) / 256, 256>>>(x, xh, MROWS * Eq);
    // 1) LN1 stats (fp32 x)
    row_stats_k<<<MROWS / 8, 256>>>(x, stats);
    // 2) qkv = LN1(x) @ in_proj_w^T + in_proj_b   (LN folded, fp16 out)
    {
        dim3 g(NQKV / 128, MROWS / 128);
        tc_gemm<0, true, false><<<g, 256, SMEM_GEMM>>>(
            xh, wqkv, nullptr, nullptr, stats, c1q, c2q, nullptr, qkv, Eq, NQKV);
    }
    // 3) batch-axis attention per (s, head)
    attn_k<<<Sq, 256>>>(qkv, obuf);
    // 4) x1 = x + o @ out_w^T + out_b   (fp32 + fp16 outputs)
    {
        dim3 g(Eq / 128, MROWS / 128);
        tc_gemm<2, true, true><<<g, 256, SMEM_GEMM>>>(
            obuf, owp, out_b, x, nullptr, nullptr, nullptr, x1, x1h, Eq, Eq);
    }
    // 5) LN2 stats (fp32 x1)
    row_stats_k<<<MROWS / 8, 256>>>(x1, stats);
    // 6) h = gelu( LN2(x1) @ w1^T + b1 )   (LN folded, fp16 out)
    {
        dim3 g(FFq / 128, MROWS / 128);
        tc_gemm<1, true, false><<<g, 256, SMEM_GEMM>>>(
            x1h, w1p, nullptr, nullptr, stats, c1f, c2f, nullptr, hbuf, Eq, FFq);
    }
    // 7) out = x1 + h @ w2^T + b2   (fp32 out)
    {
        dim3 g(Eq / 128, MROWS / 128);
        tc_gemm<2, false, true><<<g, 256, SMEM_GEMM>>>(
            hbuf, w2p, b2, x1, nullptr, nullptr, nullptr, out, nullptr, FFq, Eq);
    }
}